// round 11
// baseline (speedup 1.0000x reference)
#include <cuda_runtime.h>
#include <cuda_bf16.h>
#include <math.h>

// ---------------------------------------------------------------------------
// Causal self-attention block via mma.sync (HMMA bf16) on sm_103.
// fp32 emulation by SEGMENTED 2-plane bf16 split: operands stored as (H, L)
// tiled planes over original K; GEMM computes AhBh + AlBh + AhBl.
// R11: no __syncthreads in mainloop. Per-stage full (tx) + empty (count-128)
// mbarriers; only warp0 waits empty before stage reuse; consumers drift.
// ---------------------------------------------------------------------------

static const int Bb = 4, T = 2048, C = 1024;
static const int M = Bb * T;          // 8192

#define TILE32 8192                   // 128 rows x 32 k x 2B

// fp32 intermediates
__device__ float g_att[(size_t)4 * 2048 * 2048];
__device__ float g_v  [(size_t)8192 * 1024];
// (H,L) bf16 planes, tiled [row_stripe][chunk][8KB swizzled]
__device__ __nv_bfloat16 g_xH [(size_t)8192 * 1024];
__device__ __nv_bfloat16 g_xL [(size_t)8192 * 1024];
__device__ __nv_bfloat16 g_wqH[(size_t)3072 * 1024];
__device__ __nv_bfloat16 g_wqL[(size_t)3072 * 1024];
__device__ __nv_bfloat16 g_wpH[(size_t)1024 * 1024];
__device__ __nv_bfloat16 g_wpL[(size_t)1024 * 1024];
__device__ __nv_bfloat16 g_qH [(size_t)8192 * 1024];
__device__ __nv_bfloat16 g_qL [(size_t)8192 * 1024];
__device__ __nv_bfloat16 g_kH [(size_t)8192 * 1024];
__device__ __nv_bfloat16 g_kL [(size_t)8192 * 1024];
__device__ __nv_bfloat16 g_vtH[(size_t)4 * 1024 * 2048];
__device__ __nv_bfloat16 g_vtL[(size_t)4 * 1024 * 2048];
__device__ __nv_bfloat16 g_aH [(size_t)8192 * 2048];
__device__ __nv_bfloat16 g_aL [(size_t)8192 * 2048];
__device__ __nv_bfloat16 g_oH [(size_t)8192 * 1024];
__device__ __nv_bfloat16 g_oL [(size_t)8192 * 1024];

// swizzle for 64-byte rows (32 bf16): 16B slot c (0..3) -> c ^ ((r>>1)&3)
#define SWB32(r, c) ((unsigned)((r) * 64 + ((((c) ^ (((r) >> 1) & 3)) & 3) << 4)))

__device__ __forceinline__ void ldm4(unsigned* r, unsigned addr) {
    asm volatile("ldmatrix.sync.aligned.m8n8.x4.shared.b16 {%0,%1,%2,%3}, [%4];"
        : "=r"(r[0]), "=r"(r[1]), "=r"(r[2]), "=r"(r[3]) : "r"(addr));
}
__device__ __forceinline__ void mma16816(float* d, const unsigned* a,
                                         unsigned b0, unsigned b1) {
    asm volatile(
        "mma.sync.aligned.m16n8k16.row.col.f32.bf16.bf16.f32 "
        "{%0,%1,%2,%3}, {%4,%5,%6,%7}, {%8,%9}, {%0,%1,%2,%3};"
        : "+f"(d[0]), "+f"(d[1]), "+f"(d[2]), "+f"(d[3])
        : "r"(a[0]), "r"(a[1]), "r"(a[2]), "r"(a[3]), "r"(b0), "r"(b1));
}
__device__ __forceinline__ void bulk8k(unsigned sdst, const void* g, unsigned mb) {
    unsigned sz = TILE32;
    asm volatile(
        "cp.async.bulk.shared::cluster.global.mbarrier::complete_tx::bytes "
        "[%0], [%1], %2, [%3];"
        :: "r"(sdst), "l"(__cvta_generic_to_global(g)), "r"(sz), "r"(mb)
        : "memory");
}
__device__ __forceinline__ void mbar_wait(unsigned mbar, unsigned parity) {
    asm volatile(
        "{\n\t.reg .pred P;\n\t"
        "LW_%=:\n\t"
        "mbarrier.try_wait.parity.acquire.cta.shared::cta.b64 P, [%0], %1, 0x989680;\n\t"
        "@P bra.uni LD_%=;\n\t"
        "bra.uni LW_%=;\n\t"
        "LD_%=:\n\t}"
        :: "r"(mbar), "r"(parity) : "memory");
}
__device__ __forceinline__ void mbar_arrive(unsigned mbar) {
    asm volatile("mbarrier.arrive.release.cta.shared.b64 _, [%0];"
                 :: "r"(mbar) : "memory");
}

// split v into (h,l)
__device__ __forceinline__ void split2(float v, unsigned short& h, unsigned short& l) {
    __nv_bfloat16 hb = __float2bfloat16(v);
    __nv_bfloat16 lb = __float2bfloat16(v - __bfloat162float(hb));
    h = __bfloat16_as_ushort(hb);
    l = __bfloat16_as_ushort(lb);
}

#define STAGE_BYTES 32768 // Ah 8K + Al 8K + Bh 8K + Bl 8K
#define NSTG 3
#define GEMM_SMEM (NSTG * STAGE_BYTES + 128)

// ---------------------------------------------------------------------------
// D[M,N] = alpha * (AhBh + AlBh + AhBl) (+ bias); planes tiled+pre-swizzled.
// 128 threads, 4 warps, 64x64 warp tiles over a 128x128 CTA tile.
// emode 0: fp32 out; emode 1: plane out D1; emode 2: qkv triple.
// ---------------------------------------------------------------------------
__global__ void __launch_bounds__(128, 2)
hmma_gemm(const char* __restrict__ AH, const char* __restrict__ AL,
          const char* __restrict__ BH, const char* __restrict__ BL,
          float* __restrict__ Cf,
          char* __restrict__ D1H, char* __restrict__ D1L,
          char* __restrict__ D2H, char* __restrict__ D2L,
          float* __restrict__ Cv,
          int ncha, int nchb, int ldcf, int nchc,
          long long sAt, long long sBt, long long sC,
          float alpha, const float* __restrict__ bias,
          int causal_skip, int klimit, int K, int emode)
{
    const int row0 = blockIdx.y * 128;
    const int col0 = blockIdx.x * 128;
    if (causal_skip && col0 > row0) return;              // strictly-upper tiles
    const int kend = klimit ? min(K, row0 + 128) : K;
    const int nch = kend >> 5;                           // 32-k chunks

    const long long aoff = ((long long)blockIdx.z * sAt + (row0 >> 7) * ncha) * TILE32;
    const long long boff = ((long long)blockIdx.z * sBt + (col0 >> 7) * nchb) * TILE32;
    AH += aoff; AL += aoff; BH += boff; BL += boff;

    extern __shared__ __align__(128) unsigned char smem[];
    const unsigned sb = (unsigned)__cvta_generic_to_shared(smem);
    const unsigned mbF = sb + NSTG * STAGE_BYTES;        // full barriers
    const unsigned mbE = mbF + 8 * NSTG;                 // empty barriers

    const int tid = threadIdx.x;
    const int lane = tid & 31;
    const int wid = tid >> 5;          // 0..3
    const int wm = wid >> 1;           // 0..1 -> 64-row half
    const int wn = wid & 1;            // 0..1 -> 64-col half

    if (tid == 0) {
        #pragma unroll
        for (int s = 0; s < NSTG; s++) {
            asm volatile("mbarrier.init.shared.b64 [%0], 1;"
                         :: "r"(mbF + 8 * s) : "memory");
            asm volatile("mbarrier.init.shared.b64 [%0], 128;"
                         :: "r"(mbE + 8 * s) : "memory");
        }
    }
    __syncthreads();                   // only barrier in the whole kernel

    float acc[4][8][4];
    #pragma unroll
    for (int i = 0; i < 4; i++)
        #pragma unroll
        for (int j = 0; j < 8; j++)
            #pragma unroll
            for (int k = 0; k < 4; k++) acc[i][j][k] = 0.f;

    auto bulk_load = [&](int chunk) {      // tid0 only
        const int st = chunk % NSTG;
        if (chunk >= NSTG)                 // stage reuse: wait consumers done
            mbar_wait(mbE + 8 * st, (chunk / NSTG - 1) & 1);
        const unsigned mb = mbF + 8 * st;
        asm volatile("mbarrier.arrive.expect_tx.shared.b64 _, [%0], %1;"
                     :: "r"(mb), "r"((unsigned)STAGE_BYTES) : "memory");
        const unsigned s0 = sb + st * STAGE_BYTES;
        const size_t co = (size_t)chunk * TILE32;
        bulk8k(s0,          AH + co, mb);
        bulk8k(s0 + 8192,   AL + co, mb);
        bulk8k(s0 + 16384,  BH + co, mb);
        bulk8k(s0 + 24576,  BL + co, mb);
    };

    auto compute = [&](int chunk) {
        const int st = chunk % NSTG;
        const unsigned s0 = sb + st * STAGE_BYTES;
        mbar_wait(mbF + 8 * st, (chunk / NSTG) & 1);
        #pragma unroll
        for (int s = 0; s < 2; s++) {                    // two k16 slices
            const int ch = 2 * s + (lane >> 4);
            unsigned AhF[4][4], AlF[4][4], BhF[4][4], BlF[4][4];
            #pragma unroll
            for (int mb = 0; mb < 4; mb++) {
                const int mr = wm * 64 + mb * 16 + (lane & 15);
                ldm4(AhF[mb], s0 +         SWB32(mr, ch));
                ldm4(AlF[mb], s0 + 8192  + SWB32(mr, ch));
            }
            #pragma unroll
            for (int nb = 0; nb < 4; nb++) {
                const int nr = wn * 64 + nb * 16 + (lane & 15);
                ldm4(BhF[nb], s0 + 16384 + SWB32(nr, ch));
                ldm4(BlF[nb], s0 + 24576 + SWB32(nr, ch));
            }
            if (s == 1)                    // last smem read of this stage done
                mbar_arrive(mbE + 8 * st);
            #pragma unroll
            for (int mb = 0; mb < 4; mb++)
                #pragma unroll
                for (int nb = 0; nb < 4; nb++) {
                    mma16816(acc[mb][nb * 2 + 0], AhF[mb], BhF[nb][0], BhF[nb][2]);
                    mma16816(acc[mb][nb * 2 + 1], AhF[mb], BhF[nb][1], BhF[nb][3]);
                }
            #pragma unroll
            for (int mb = 0; mb < 4; mb++)
                #pragma unroll
                for (int nb = 0; nb < 4; nb++) {
                    mma16816(acc[mb][nb * 2 + 0], AlF[mb], BhF[nb][0], BhF[nb][2]);
                    mma16816(acc[mb][nb * 2 + 1], AlF[mb], BhF[nb][1], BhF[nb][3]);
                }
            #pragma unroll
            for (int mb = 0; mb < 4; mb++)
                #pragma unroll
                for (int nb = 0; nb < 4; nb++) {
                    mma16816(acc[mb][nb * 2 + 0], AhF[mb], BlF[nb][0], BlF[nb][2]);
                    mma16816(acc[mb][nb * 2 + 1], AhF[mb], BlF[nb][1], BlF[nb][3]);
                }
        }
    };

    if (tid == 0) {
        bulk_load(0);
        if (nch > 1) bulk_load(1);
    }
    for (int i = 0; i < nch; i++) {
        if (tid == 0 && i + 2 < nch) bulk_load(i + 2);
        compute(i);
    }

    // ----- epilogue (per-warp registers only; no cross-warp deps) -----
    char *dH = 0, *dL = 0;
    int colr = col0;
    float* df = 0;
    int ldf = ldcf;
    long long ztile = 0;
    if (emode == 0) {
        df = Cf + (long long)blockIdx.z * sC;
    } else if (emode == 1) {
        dH = D1H; dL = D1L; ztile = (long long)blockIdx.z * sC;   // sC in tiles
    } else {                                  // qkv triple
        if (col0 < 1024)      { dH = D1H; dL = D1L; colr = col0; }
        else if (col0 < 2048) { dH = D2H; dL = D2L; colr = col0 - 1024; }
        else                  { df = Cv; ldf = 1024; colr = col0 - 2048; }
    }

    const int cbase = wn * 64 + 2 * (lane & 3);
    #pragma unroll
    for (int mb = 0; mb < 4; mb++) {
        #pragma unroll
        for (int half = 0; half < 2; half++) {
            const int r = row0 + wm * 64 + mb * 16 + (lane >> 2) + half * 8;
            const long long tb = dH ? (ztile + (long long)(r >> 7) * nchc) * TILE32 : 0;
            const int lr = r & 127;
            #pragma unroll
            for (int nb = 0; nb < 8; nb++) {
                const int cr = colr + cbase + nb * 8;    // region-relative (even)
                const int ca = col0 + cbase + nb * 8;    // absolute (bias)
                float vx = acc[mb][nb][half * 2 + 0] * alpha;
                float vy = acc[mb][nb][half * 2 + 1] * alpha;
                if (bias) { vx += bias[ca]; vy += bias[ca + 1]; }
                if (dH) {
                    unsigned short hx, lx, hy, ly;
                    split2(vx, hx, lx);
                    split2(vy, hy, ly);
                    const int byte = 2 * cr;             // multiple of 4
                    const unsigned off = (unsigned)(byte >> 6) * TILE32
                                       + SWB32(lr, (byte & 63) >> 4) + (byte & 15);
                    *(unsigned*)(dH + tb + off) = (unsigned)hx | ((unsigned)hy << 16);
                    *(unsigned*)(dL + tb + off) = (unsigned)lx | ((unsigned)ly << 16);
                } else {
                    *(float2*)(df + (long long)r * ldf + cr) = make_float2(vx, vy);
                }
            }
        }
    }
}

// ---------------------------------------------------------------------------
// fp32 -> (h,l) planes, tiled+swizzled output
// ---------------------------------------------------------------------------
__global__ void split2_kernel(const float* __restrict__ in,
                              __nv_bfloat16* __restrict__ outH,
                              __nv_bfloat16* __restrict__ outL,
                              int R, int Cin, int ld)
{
    const int c8n = Cin >> 3;
    long long idx = (long long)blockIdx.x * blockDim.x + threadIdx.x;
    if (idx >= (long long)R * c8n) return;
    const int r = (int)(idx / c8n);
    const int c = (int)(idx - (long long)r * c8n) * 8;

    const float4 v0 = *(const float4*)(in + (long long)r * ld + c);
    const float4 v1 = *(const float4*)(in + (long long)r * ld + c + 4);
    float f[8] = {v0.x, v0.y, v0.z, v0.w, v1.x, v1.y, v1.z, v1.w};

    alignas(16) unsigned short h[8], l[8];
    #pragma unroll
    for (int j = 0; j < 8; j++) split2(f[j], h[j], l[j]);

    const int nch = Cin >> 5;
    const size_t base = (size_t)(r >> 7) * nch * TILE32;
    const int lr = r & 127;
    const int byte = 2 * c;                   // multiple of 16
    const unsigned off = (unsigned)(byte >> 6) * TILE32
                       + SWB32(lr, (byte & 63) >> 4);
    *(uint4*)((char*)outH + base + off) = *(uint4*)h;
    *(uint4*)((char*)outL + base + off) = *(uint4*)l;
}

// V[s,c] fp32 [8192,1024] -> vt planes: batch b, row=channel, k=token
__global__ void transpose_split2_kernel(const float* __restrict__ v,
                                        __nv_bfloat16* __restrict__ vtH,
                                        __nv_bfloat16* __restrict__ vtL)
{
    __shared__ float tile[32][33];
    const int b = blockIdx.z;
    const int s0 = blockIdx.x * 32, c0 = blockIdx.y * 32;
    const int tx = threadIdx.x, ty = threadIdx.y;
    tile[ty][tx] = v[((long long)(b * 2048 + s0 + ty)) * 1024 + c0 + tx];
    __syncthreads();
    unsigned short h, l;
    split2(tile[tx][ty], h, l);
    const int row = c0 + ty;                  // channel 0..1023
    const int ss = s0 + tx;                   // token
    const size_t base = (size_t)(b * 8 * 64 + (row >> 7) * 64) * TILE32;
    const int lr = row & 127;
    const int byte = 2 * ss;
    const unsigned off = (unsigned)(byte >> 6) * TILE32
                       + SWB32(lr, (byte & 63) >> 4) + (byte & 15);
    *(unsigned short*)((char*)vtH + base + off) = h;
    *(unsigned short*)((char*)vtL + base + off) = l;
}

// ---------------------------------------------------------------------------
// FMA-pipe exp for x <= 0 (MUFU EX2 is quarter-rate on B300).
// ---------------------------------------------------------------------------
__device__ __forceinline__ float fexp(float x) {
    float y = x * 1.4426950408889634f;
    float n = floorf(y);
    float f = y - n;
    float p = 0.000154035304f;
    p = fmaf(p, f, 0.00133335581f);
    p = fmaf(p, f, 0.00961812910f);
    p = fmaf(p, f, 0.0555041087f);
    p = fmaf(p, f, 0.240226507f);
    p = fmaf(p, f, 0.693147180f);
    p = fmaf(p, f, 1.0f);
    int ni = (int)n;
    if (ni < -126) return 0.f;
    return p * __int_as_float((ni + 127) << 23);
}

// ---------------------------------------------------------------------------
// causal softmax: fp32 scores -> (h,l) att planes (tiled, tile-bounded writes)
// ---------------------------------------------------------------------------
__global__ void softmax_split_kernel(const float* __restrict__ att,
                                     __nv_bfloat16* __restrict__ attH,
                                     __nv_bfloat16* __restrict__ attL, int Tn)
{
    __shared__ float buf[2048];
    __shared__ float red[256];
    const int row = blockIdx.x;
    const int t = row % Tn;
    const float* p = att + (long long)row * Tn;
    const int tid = threadIdx.x;
    const int len = t + 1;
    const int lenR = (t & ~127) + 128;        // = row-tile boundary

    float m = -1e30f;
    for (int s = tid; s < len; s += 256) { float v = p[s]; buf[s] = v; m = fmaxf(m, v); }
    red[tid] = m; __syncthreads();
    for (int off = 128; off > 0; off >>= 1) {
        if (tid < off) red[tid] = fmaxf(red[tid], red[tid + off]);
        __syncthreads();
    }
    m = red[0]; __syncthreads();

    float sum = 0.f;
    for (int s = tid; s < len; s += 256) {
        float e = fexp(buf[s] - m);
        buf[s] = e;
        sum += e;
    }
    red[tid] = sum; __syncthreads();
    for (int off = 128; off > 0; off >>= 1) {
        if (tid < off) red[tid] += red[tid + off];
        __syncthreads();
    }
    const float inv = 1.f / red[0];
    __syncthreads();

    const int s8 = tid * 8;                   // 8 tokens per thread
    if (s8 < lenR) {
        alignas(16) unsigned short h[8], l[8];
        #pragma unroll
        for (int j = 0; j < 8; j++) {
            const int s = s8 + j;
            const float e = (s < len) ? buf[s] * inv : 0.f;
            split2(e, h[j], l[j]);
        }
        const size_t base = (size_t)(row >> 7) * 64 * TILE32;
        const int lr = row & 127;
        const int byte = 2 * s8;
        const unsigned off = (unsigned)(byte >> 6) * TILE32
                           + SWB32(lr, (byte & 63) >> 4);
        *(uint4*)((char*)attH + base + off) = *(uint4*)h;
        *(uint4*)((char*)attL + base + off) = *(uint4*)l;
    }
}

// ---------------------------------------------------------------------------
extern "C" void kernel_launch(void* const* d_in, const int* in_sizes, int n_in,
                              void* d_out, int out_size)
{
    const float* x      = (const float*)d_in[0];
    const float* w_qkv  = (const float*)d_in[1];
    const float* b_qkv  = (const float*)d_in[2];
    const float* w_proj = (const float*)d_in[3];
    const float* b_proj = (const float*)d_in[4];
    float* out = (float*)d_out;

    float *att, *v;
    __nv_bfloat16 *xH, *xL, *wqH, *wqL, *wpH, *wpL;
    __nv_bfloat16 *qH, *qL, *kH, *kL, *vtH, *vtL, *aH, *aL, *oH, *oL;
    cudaGetSymbolAddress((void**)&att, g_att);
    cudaGetSymbolAddress((void**)&v,   g_v);
    cudaGetSymbolAddress((void**)&xH,  g_xH);  cudaGetSymbolAddress((void**)&xL,  g_xL);
    cudaGetSymbolAddress((void**)&wqH, g_wqH); cudaGetSymbolAddress((void**)&wqL, g_wqL);
    cudaGetSymbolAddress((void**)&wpH, g_wpH); cudaGetSymbolAddress((void**)&wpL, g_wpL);
    cudaGetSymbolAddress((void**)&qH,  g_qH);  cudaGetSymbolAddress((void**)&qL,  g_qL);
    cudaGetSymbolAddress((void**)&kH,  g_kH);  cudaGetSymbolAddress((void**)&kL,  g_kL);
    cudaGetSymbolAddress((void**)&vtH, g_vtH); cudaGetSymbolAddress((void**)&vtL, g_vtL);
    cudaGetSymbolAddress((void**)&aH,  g_aH);  cudaGetSymbolAddress((void**)&aL,  g_aL);
    cudaGetSymbolAddress((void**)&oH,  g_oH);  cudaGetSymbolAddress((void**)&oL,  g_oL);

    cudaFuncSetAttribute(hmma_gemm,
        cudaFuncAttributeMaxDynamicSharedMemorySize, GEMM_SMEM);

    const float inv_sqrt_c = 0.03125f;

    // split the raw inputs into (h,l) planes
    split2_kernel<<<(M * (C / 8) + 255) / 256, 256>>>(x, xH, xL, M, C, C);
    split2_kernel<<<(3 * C * (C / 8) + 255) / 256, 256>>>(w_qkv, wqH, wqL, 3 * C, C, C);
    split2_kernel<<<(C * (C / 8) + 255) / 256, 256>>>(w_proj, wpH, wpL, C, C, C);

    // 1) qkv GEMM -> q planes / k planes / v (fp32)
    hmma_gemm<<<dim3(3 * C / 128, M / 128, 1), 128, GEMM_SMEM>>>(
        (const char*)xH, (const char*)xL, (const char*)wqH, (const char*)wqL,
        nullptr, (char*)qH, (char*)qL, (char*)kH, (char*)kL, v,
        32, 32, 0, 32, 0, 0, 0,
        1.f, b_qkv, 0, 0, C, 2);

    // transpose-split v -> vt planes
    transpose_split2_kernel<<<dim3(T / 32, C / 32, Bb), dim3(32, 32)>>>(v, vtH, vtL);

    // 2) scores = (q @ k^T) / sqrt(C), causal tile-skip, fp32 out
    hmma_gemm<<<dim3(T / 128, T / 128, Bb), 128, GEMM_SMEM>>>(
        (const char*)qH, (const char*)qL, (const char*)kH, (const char*)kL,
        att, nullptr, nullptr, nullptr, nullptr, nullptr,
        32, 32, T, 0,
        16 * 32, 16 * 32, (long long)T * T,
        inv_sqrt_c, nullptr, 1, 0, C, 0);

    // 3) softmax -> att planes (tile-bounded writes)
    softmax_split_kernel<<<M, 256>>>(att, aH, aL, T);

    // 4) o = att @ V  (k-limited) -> o planes
    hmma_gemm<<<dim3(C / 128, T / 128, Bb), 128, GEMM_SMEM>>>(
        (const char*)aH, (const char*)aL, (const char*)vtH, (const char*)vtL,
        nullptr, (char*)oH, (char*)oL, nullptr, nullptr, nullptr,
        64, 64, 0, 32,
        16 * 64, 8 * 64, 16 * 32,
        1.f, nullptr, 0, 1, T, 1);

    // 5) out = o @ w_proj^T + b_proj   (fp32 out)
    hmma_gemm<<<dim3(C / 128, M / 128, 1), 128, GEMM_SMEM>>>(
        (const char*)oH, (const char*)oL, (const char*)wpH, (const char*)wpL,
        out, nullptr, nullptr, nullptr, nullptr, nullptr,
        32, 32, C, 0, 0, 0, 0,
        1.f, b_proj, 0, 0, C, 0);
}

// round 12
// speedup vs baseline: 1.0326x; 1.0326x over previous
#include <cuda_runtime.h>
#include <cuda_bf16.h>
#include <math.h>

// ---------------------------------------------------------------------------
// Causal self-attention block via mma.sync (HMMA bf16) on sm_103.
// fp32 emulation by SEGMENTED 2-plane bf16 split (H,L over original K);
// GEMM computes AhBh + AlBh + AhBl (drops only AlBl ~2^-18).
// R12: algebraic refactor out = att @ (Wp·V^T)^T — deletes V transpose,
// o-planes, one kernel; qkv emits V planes directly. Mainloop interleaves
// LDSM at product granularity + warp-parity slice stagger.
// ---------------------------------------------------------------------------

static const int Bb = 4, T = 2048, C = 1024;
static const int M = Bb * T;          // 8192

#define TILE32 8192                   // 128 rows x 32 k x 2B

// fp32 intermediates
__device__ float g_att[(size_t)4 * 2048 * 2048];
// (H,L) bf16 planes, tiled [row_stripe][chunk][8KB swizzled]
__device__ __nv_bfloat16 g_xH [(size_t)8192 * 1024];
__device__ __nv_bfloat16 g_xL [(size_t)8192 * 1024];
__device__ __nv_bfloat16 g_wqH[(size_t)3072 * 1024];
__device__ __nv_bfloat16 g_wqL[(size_t)3072 * 1024];
__device__ __nv_bfloat16 g_wpH[(size_t)1024 * 1024];
__device__ __nv_bfloat16 g_wpL[(size_t)1024 * 1024];
__device__ __nv_bfloat16 g_qH [(size_t)8192 * 1024];
__device__ __nv_bfloat16 g_qL [(size_t)8192 * 1024];
__device__ __nv_bfloat16 g_kH [(size_t)8192 * 1024];
__device__ __nv_bfloat16 g_kL [(size_t)8192 * 1024];
__device__ __nv_bfloat16 g_vH [(size_t)8192 * 1024];
__device__ __nv_bfloat16 g_vL [(size_t)8192 * 1024];
__device__ __nv_bfloat16 g_vwH[(size_t)4 * 1024 * 2048];
__device__ __nv_bfloat16 g_vwL[(size_t)4 * 1024 * 2048];
__device__ __nv_bfloat16 g_aH [(size_t)8192 * 2048];
__device__ __nv_bfloat16 g_aL [(size_t)8192 * 2048];

// swizzle for 64-byte rows (32 bf16): 16B slot c (0..3) -> c ^ ((r>>1)&3)
#define SWB32(r, c) ((unsigned)((r) * 64 + ((((c) ^ (((r) >> 1) & 3)) & 3) << 4)))

__device__ __forceinline__ void ldm4(unsigned* r, unsigned addr) {
    asm volatile("ldmatrix.sync.aligned.m8n8.x4.shared.b16 {%0,%1,%2,%3}, [%4];"
        : "=r"(r[0]), "=r"(r[1]), "=r"(r[2]), "=r"(r[3]) : "r"(addr));
}
__device__ __forceinline__ void mma16816(float* d, const unsigned* a,
                                         unsigned b0, unsigned b1) {
    asm volatile(
        "mma.sync.aligned.m16n8k16.row.col.f32.bf16.bf16.f32 "
        "{%0,%1,%2,%3}, {%4,%5,%6,%7}, {%8,%9}, {%0,%1,%2,%3};"
        : "+f"(d[0]), "+f"(d[1]), "+f"(d[2]), "+f"(d[3])
        : "r"(a[0]), "r"(a[1]), "r"(a[2]), "r"(a[3]), "r"(b0), "r"(b1));
}
__device__ __forceinline__ void bulk8k(unsigned sdst, const void* g, unsigned mb) {
    unsigned sz = TILE32;
    asm volatile(
        "cp.async.bulk.shared::cluster.global.mbarrier::complete_tx::bytes "
        "[%0], [%1], %2, [%3];"
        :: "r"(sdst), "l"(__cvta_generic_to_global(g)), "r"(sz), "r"(mb)
        : "memory");
}
__device__ __forceinline__ void mbar_wait(unsigned mbar, unsigned parity) {
    asm volatile(
        "{\n\t.reg .pred P;\n\t"
        "LW_%=:\n\t"
        "mbarrier.try_wait.parity.acquire.cta.shared::cta.b64 P, [%0], %1, 0x989680;\n\t"
        "@P bra.uni LD_%=;\n\t"
        "bra.uni LW_%=;\n\t"
        "LD_%=:\n\t}"
        :: "r"(mbar), "r"(parity) : "memory");
}
__device__ __forceinline__ void mbar_arrive(unsigned mbar) {
    asm volatile("mbarrier.arrive.release.cta.shared.b64 _, [%0];"
                 :: "r"(mbar) : "memory");
}

__device__ __forceinline__ void split2(float v, unsigned short& h, unsigned short& l) {
    __nv_bfloat16 hb = __float2bfloat16(v);
    __nv_bfloat16 lb = __float2bfloat16(v - __bfloat162float(hb));
    h = __bfloat16_as_ushort(hb);
    l = __bfloat16_as_ushort(lb);
}

#define STAGE_BYTES 32768 // Ah 8K + Al 8K + Bh 8K + Bl 8K
#define NSTG 3
#define GEMM_SMEM (NSTG * STAGE_BYTES + 128)

// ---------------------------------------------------------------------------
// D[M,N] = alpha * (AhBh + AlBh + AhBl) (+ bias); planes tiled+pre-swizzled.
// 128 threads, 4 warps, 64x64 warp tiles over a 128x128 CTA tile.
// emode 0: fp32 out (Cf); emode 1: plane out D1;
// emode 2: qkv triple -> D1 (q), D2 (k), D3 (v), all plane pairs (nchc).
// ---------------------------------------------------------------------------
__global__ void __launch_bounds__(128, 2)
hmma_gemm(const char* __restrict__ AH, const char* __restrict__ AL,
          const char* __restrict__ BH, const char* __restrict__ BL,
          float* __restrict__ Cf,
          char* __restrict__ D1H, char* __restrict__ D1L,
          char* __restrict__ D2H, char* __restrict__ D2L,
          char* __restrict__ D3H, char* __restrict__ D3L,
          int ncha, int nchb, int ldcf, int nchc,
          long long sAt, long long sBt, long long sC,
          float alpha, const float* __restrict__ bias,
          int causal_skip, int klimit, int K, int emode)
{
    const int row0 = blockIdx.y * 128;
    const int col0 = blockIdx.x * 128;
    if (causal_skip && col0 > row0) return;              // strictly-upper tiles
    const int kend = klimit ? min(K, row0 + 128) : K;
    const int nch = kend >> 5;                           // 32-k chunks

    const long long aoff = ((long long)blockIdx.z * sAt + (row0 >> 7) * ncha) * TILE32;
    const long long boff = ((long long)blockIdx.z * sBt + (col0 >> 7) * nchb) * TILE32;
    AH += aoff; AL += aoff; BH += boff; BL += boff;

    extern __shared__ __align__(128) unsigned char smem[];
    const unsigned sb = (unsigned)__cvta_generic_to_shared(smem);
    const unsigned mbF = sb + NSTG * STAGE_BYTES;        // full barriers
    const unsigned mbE = mbF + 8 * NSTG;                 // empty barriers

    const int tid = threadIdx.x;
    const int lane = tid & 31;
    const int wid = tid >> 5;          // 0..3
    const int wm = wid >> 1;           // 0..1 -> 64-row half
    const int wn = wid & 1;            // 0..1 -> 64-col half

    if (tid == 0) {
        #pragma unroll
        for (int s = 0; s < NSTG; s++) {
            asm volatile("mbarrier.init.shared.b64 [%0], 1;"
                         :: "r"(mbF + 8 * s) : "memory");
            asm volatile("mbarrier.init.shared.b64 [%0], 128;"
                         :: "r"(mbE + 8 * s) : "memory");
        }
    }
    __syncthreads();

    float acc[4][8][4];
    #pragma unroll
    for (int i = 0; i < 4; i++)
        #pragma unroll
        for (int j = 0; j < 8; j++)
            #pragma unroll
            for (int k = 0; k < 4; k++) acc[i][j][k] = 0.f;

    auto bulk_load = [&](int chunk) {      // tid0 only
        const int st = chunk % NSTG;
        if (chunk >= NSTG)
            mbar_wait(mbE + 8 * st, (chunk / NSTG - 1) & 1);
        const unsigned mb = mbF + 8 * st;
        asm volatile("mbarrier.arrive.expect_tx.shared.b64 _, [%0], %1;"
                     :: "r"(mb), "r"((unsigned)STAGE_BYTES) : "memory");
        const unsigned s0 = sb + st * STAGE_BYTES;
        const size_t co = (size_t)chunk * TILE32;
        bulk8k(s0,          AH + co, mb);
        bulk8k(s0 + 8192,   AL + co, mb);
        bulk8k(s0 + 16384,  BH + co, mb);
        bulk8k(s0 + 24576,  BL + co, mb);
    };

    const int sfirst = wid & 1;       // warp-parity slice stagger
    auto compute = [&](int chunk) {
        const int st = chunk % NSTG;
        const unsigned s0 = sb + st * STAGE_BYTES;
        mbar_wait(mbF + 8 * st, (chunk / NSTG) & 1);
        #pragma unroll
        for (int si = 0; si < 2; si++) {
            const int s = si ^ sfirst;
            const int ch = 2 * s + (lane >> 4);
            unsigned AhF[4][4], AlF[4][4], BhF[4][4], BlF[4][4];
            // phase 1: load Ah, Bh
            #pragma unroll
            for (int mb = 0; mb < 4; mb++) {
                const int mr = wm * 64 + mb * 16 + (lane & 15);
                ldm4(AhF[mb], s0 + SWB32(mr, ch));
            }
            #pragma unroll
            for (int nb = 0; nb < 4; nb++) {
                const int nr = wn * 64 + nb * 16 + (lane & 15);
                ldm4(BhF[nb], s0 + 16384 + SWB32(nr, ch));
            }
            // product 1: Ah*Bh
            #pragma unroll
            for (int mb = 0; mb < 4; mb++)
                #pragma unroll
                for (int nb = 0; nb < 4; nb++) {
                    mma16816(acc[mb][nb * 2 + 0], AhF[mb], BhF[nb][0], BhF[nb][2]);
                    mma16816(acc[mb][nb * 2 + 1], AhF[mb], BhF[nb][1], BhF[nb][3]);
                }
            // phase 2: load Al
            #pragma unroll
            for (int mb = 0; mb < 4; mb++) {
                const int mr = wm * 64 + mb * 16 + (lane & 15);
                ldm4(AlF[mb], s0 + 8192 + SWB32(mr, ch));
            }
            // product 2: Al*Bh
            #pragma unroll
            for (int mb = 0; mb < 4; mb++)
                #pragma unroll
                for (int nb = 0; nb < 4; nb++) {
                    mma16816(acc[mb][nb * 2 + 0], AlF[mb], BhF[nb][0], BhF[nb][2]);
                    mma16816(acc[mb][nb * 2 + 1], AlF[mb], BhF[nb][1], BhF[nb][3]);
                }
            // phase 3: load Bl
            #pragma unroll
            for (int nb = 0; nb < 4; nb++) {
                const int nr = wn * 64 + nb * 16 + (lane & 15);
                ldm4(BlF[nb], s0 + 24576 + SWB32(nr, ch));
            }
            if (si == 1)                   // last smem read of this stage
                mbar_arrive(mbE + 8 * st);
            // product 3: Ah*Bl
            #pragma unroll
            for (int mb = 0; mb < 4; mb++)
                #pragma unroll
                for (int nb = 0; nb < 4; nb++) {
                    mma16816(acc[mb][nb * 2 + 0], AhF[mb], BlF[nb][0], BlF[nb][2]);
                    mma16816(acc[mb][nb * 2 + 1], AhF[mb], BlF[nb][1], BlF[nb][3]);
                }
        }
    };

    if (tid == 0) {
        bulk_load(0);
        if (nch > 1) bulk_load(1);
    }
    for (int i = 0; i < nch; i++) {
        if (tid == 0 && i + 2 < nch) bulk_load(i + 2);
        compute(i);
    }

    // ----- epilogue -----
    char *dH = 0, *dL = 0;
    int colr = col0;
    float* df = 0;
    long long ztile = 0;
    if (emode == 0) {
        df = Cf + (long long)blockIdx.z * sC;
    } else if (emode == 1) {
        dH = D1H; dL = D1L; ztile = (long long)blockIdx.z * sC;   // sC in tiles
    } else {                                  // qkv triple
        if (col0 < 1024)      { dH = D1H; dL = D1L; colr = col0; }
        else if (col0 < 2048) { dH = D2H; dL = D2L; colr = col0 - 1024; }
        else                  { dH = D3H; dL = D3L; colr = col0 - 2048; }
    }

    const int cbase = wn * 64 + 2 * (lane & 3);
    #pragma unroll
    for (int mb = 0; mb < 4; mb++) {
        #pragma unroll
        for (int half = 0; half < 2; half++) {
            const int r = row0 + wm * 64 + mb * 16 + (lane >> 2) + half * 8;
            const long long tb = dH ? (ztile + (long long)(r >> 7) * nchc) * TILE32 : 0;
            const int lr = r & 127;
            #pragma unroll
            for (int nb = 0; nb < 8; nb++) {
                const int cr = colr + cbase + nb * 8;    // region-relative (even)
                const int ca = col0 + cbase + nb * 8;    // absolute (bias)
                float vx = acc[mb][nb][half * 2 + 0] * alpha;
                float vy = acc[mb][nb][half * 2 + 1] * alpha;
                if (bias) { vx += bias[ca]; vy += bias[ca + 1]; }
                if (dH) {
                    unsigned short hx, lx, hy, ly;
                    split2(vx, hx, lx);
                    split2(vy, hy, ly);
                    const int byte = 2 * cr;             // multiple of 4
                    const unsigned off = (unsigned)(byte >> 6) * TILE32
                                       + SWB32(lr, (byte & 63) >> 4) + (byte & 15);
                    *(unsigned*)(dH + tb + off) = (unsigned)hx | ((unsigned)hy << 16);
                    *(unsigned*)(dL + tb + off) = (unsigned)lx | ((unsigned)ly << 16);
                } else {
                    *(float2*)(df + (long long)r * ldcf + cr) = make_float2(vx, vy);
                }
            }
        }
    }
}

// ---------------------------------------------------------------------------
// fp32 -> (h,l) planes, tiled+swizzled output
// ---------------------------------------------------------------------------
__global__ void split2_kernel(const float* __restrict__ in,
                              __nv_bfloat16* __restrict__ outH,
                              __nv_bfloat16* __restrict__ outL,
                              int R, int Cin, int ld)
{
    const int c8n = Cin >> 3;
    long long idx = (long long)blockIdx.x * blockDim.x + threadIdx.x;
    if (idx >= (long long)R * c8n) return;
    const int r = (int)(idx / c8n);
    const int c = (int)(idx - (long long)r * c8n) * 8;

    const float4 v0 = *(const float4*)(in + (long long)r * ld + c);
    const float4 v1 = *(const float4*)(in + (long long)r * ld + c + 4);
    float f[8] = {v0.x, v0.y, v0.z, v0.w, v1.x, v1.y, v1.z, v1.w};

    alignas(16) unsigned short h[8], l[8];
    #pragma unroll
    for (int j = 0; j < 8; j++) split2(f[j], h[j], l[j]);

    const int nch = Cin >> 5;
    const size_t base = (size_t)(r >> 7) * nch * TILE32;
    const int lr = r & 127;
    const int byte = 2 * c;                   // multiple of 16
    const unsigned off = (unsigned)(byte >> 6) * TILE32
                       + SWB32(lr, (byte & 63) >> 4);
    *(uint4*)((char*)outH + base + off) = *(uint4*)h;
    *(uint4*)((char*)outL + base + off) = *(uint4*)l;
}

// ---------------------------------------------------------------------------
// FMA-pipe exp for x <= 0 (MUFU EX2 is quarter-rate on B300).
// ---------------------------------------------------------------------------
__device__ __forceinline__ float fexp(float x) {
    float y = x * 1.4426950408889634f;
    float n = floorf(y);
    float f = y - n;
    float p = 0.000154035304f;
    p = fmaf(p, f, 0.00133335581f);
    p = fmaf(p, f, 0.00961812910f);
    p = fmaf(p, f, 0.0555041087f);
    p = fmaf(p, f, 0.240226507f);
    p = fmaf(p, f, 0.693147180f);
    p = fmaf(p, f, 1.0f);
    int ni = (int)n;
    if (ni < -126) return 0.f;
    return p * __int_as_float((ni + 127) << 23);
}

// ---------------------------------------------------------------------------
// causal softmax: fp32 scores -> (h,l) att planes (tiled, tile-bounded writes)
// ---------------------------------------------------------------------------
__global__ void softmax_split_kernel(const float* __restrict__ att,
                                     __nv_bfloat16* __restrict__ attH,
                                     __nv_bfloat16* __restrict__ attL, int Tn)
{
    __shared__ float buf[2048];
    __shared__ float red[256];
    const int row = blockIdx.x;
    const int t = row % Tn;
    const float* p = att + (long long)row * Tn;
    const int tid = threadIdx.x;
    const int len = t + 1;
    const int lenR = (t & ~127) + 128;        // = row-tile boundary

    float m = -1e30f;
    for (int s = tid; s < len; s += 256) { float v = p[s]; buf[s] = v; m = fmaxf(m, v); }
    red[tid] = m; __syncthreads();
    for (int off = 128; off > 0; off >>= 1) {
        if (tid < off) red[tid] = fmaxf(red[tid], red[tid + off]);
        __syncthreads();
    }
    m = red[0]; __syncthreads();

    float sum = 0.f;
    for (int s = tid; s < len; s += 256) {
        float e = fexp(buf[s] - m);
        buf[s] = e;
        sum += e;
    }
    red[tid] = sum; __syncthreads();
    for (int off = 128; off > 0; off >>= 1) {
        if (tid < off) red[tid] += red[tid + off];
        __syncthreads();
    }
    const float inv = 1.f / red[0];
    __syncthreads();

    const int s8 = tid * 8;                   // 8 tokens per thread
    if (s8 < lenR) {
        alignas(16) unsigned short h[8], l[8];
        #pragma unroll
        for (int j = 0; j < 8; j++) {
            const int s = s8 + j;
            const float e = (s < len) ? buf[s] * inv : 0.f;
            split2(e, h[j], l[j]);
        }
        const size_t base = (size_t)(row >> 7) * 64 * TILE32;
        const int lr = row & 127;
        const int byte = 2 * s8;
        const unsigned off = (unsigned)(byte >> 6) * TILE32
                           + SWB32(lr, (byte & 63) >> 4);
        *(uint4*)((char*)attH + base + off) = *(uint4*)h;
        *(uint4*)((char*)attL + base + off) = *(uint4*)l;
    }
}

// ---------------------------------------------------------------------------
extern "C" void kernel_launch(void* const* d_in, const int* in_sizes, int n_in,
                              void* d_out, int out_size)
{
    const float* x      = (const float*)d_in[0];
    const float* w_qkv  = (const float*)d_in[1];
    const float* b_qkv  = (const float*)d_in[2];
    const float* w_proj = (const float*)d_in[3];
    const float* b_proj = (const float*)d_in[4];
    float* out = (float*)d_out;

    float *att;
    __nv_bfloat16 *xH, *xL, *wqH, *wqL, *wpH, *wpL;
    __nv_bfloat16 *qH, *qL, *kH, *kL, *vH, *vL, *vwH, *vwL, *aH, *aL;
    cudaGetSymbolAddress((void**)&att, g_att);
    cudaGetSymbolAddress((void**)&xH,  g_xH);  cudaGetSymbolAddress((void**)&xL,  g_xL);
    cudaGetSymbolAddress((void**)&wqH, g_wqH); cudaGetSymbolAddress((void**)&wqL, g_wqL);
    cudaGetSymbolAddress((void**)&wpH, g_wpH); cudaGetSymbolAddress((void**)&wpL, g_wpL);
    cudaGetSymbolAddress((void**)&qH,  g_qH);  cudaGetSymbolAddress((void**)&qL,  g_qL);
    cudaGetSymbolAddress((void**)&kH,  g_kH);  cudaGetSymbolAddress((void**)&kL,  g_kL);
    cudaGetSymbolAddress((void**)&vH,  g_vH);  cudaGetSymbolAddress((void**)&vL,  g_vL);
    cudaGetSymbolAddress((void**)&vwH, g_vwH); cudaGetSymbolAddress((void**)&vwL, g_vwL);
    cudaGetSymbolAddress((void**)&aH,  g_aH);  cudaGetSymbolAddress((void**)&aL,  g_aL);

    cudaFuncSetAttribute(hmma_gemm,
        cudaFuncAttributeMaxDynamicSharedMemorySize, GEMM_SMEM);

    const float inv_sqrt_c = 0.03125f;

    // split the raw inputs into (h,l) planes
    split2_kernel<<<(M * (C / 8) + 255) / 256, 256>>>(x, xH, xL, M, C, C);
    split2_kernel<<<(3 * C * (C / 8) + 255) / 256, 256>>>(w_qkv, wqH, wqL, 3 * C, C, C);
    split2_kernel<<<(C * (C / 8) + 255) / 256, 256>>>(w_proj, wpH, wpL, C, C, C);

    // 1) qkv GEMM -> q / k / v planes
    hmma_gemm<<<dim3(3 * C / 128, M / 128, 1), 128, GEMM_SMEM>>>(
        (const char*)xH, (const char*)xL, (const char*)wqH, (const char*)wqL,
        nullptr, (char*)qH, (char*)qL, (char*)kH, (char*)kL, (char*)vH, (char*)vL,
        32, 32, 0, 32, 0, 0, 0,
        1.f, b_qkv, 0, 0, C, 2);

    // 2) VWt[c,s] = Wp @ V^T per batch -> vw planes [c rows, s chunks]
    hmma_gemm<<<dim3(T / 128, C / 128, Bb), 128, GEMM_SMEM>>>(
        (const char*)wpH, (const char*)wpL, (const char*)vH, (const char*)vL,
        nullptr, (char*)vwH, (char*)vwL, nullptr, nullptr, nullptr, nullptr,
        32, 32, 0, 64,
        0, 16 * 32, 8 * 64,
        1.f, nullptr, 0, 0, C, 1);

    // 3) scores = (q @ k^T) / sqrt(C), causal tile-skip, fp32 out
    hmma_gemm<<<dim3(T / 128, T / 128, Bb), 128, GEMM_SMEM>>>(
        (const char*)qH, (const char*)qL, (const char*)kH, (const char*)kL,
        att, nullptr, nullptr, nullptr, nullptr, nullptr, nullptr,
        32, 32, T, 0,
        16 * 32, 16 * 32, (long long)T * T,
        inv_sqrt_c, nullptr, 1, 0, C, 0);

    // 4) softmax -> att planes (tile-bounded writes)
    softmax_split_kernel<<<M, 256>>>(att, aH, aL, T);

    // 5) out = att @ VWt^T + b_proj  (k-limited by causality, fp32 out)
    hmma_gemm<<<dim3(C / 128, T / 128, Bb), 128, GEMM_SMEM>>>(
        (const char*)aH, (const char*)aL, (const char*)vwH, (const char*)vwL,
        out, nullptr, nullptr, nullptr, nullptr, nullptr, nullptr,
        64, 64, C, 0,
        16 * 64, 8 * 64, (long long)T * C,
        1.f, b_proj, 0, 1, T, 0);
}